// round 2
// baseline (speedup 1.0000x reference)
#include <cuda_runtime.h>
#include <cuda_fp16.h>
#include <cstdint>
#include <math.h>

// ----------------------------------------------------------------------------
// LorentzLinear without 'a'-suffix ISA features (harness targets compute_103):
// Ampere-style fp16 mma.sync GEMM (fp32 accum) + fused Lorentz epilogue.
//
// CTA: 128 rows x 512 cols, as two N-chunks of 256 (512 thr, 16 warps 4x4).
// Chunk 0 output stashed in smem (128x256 fp32), chunk 1 kept in registers.
// Per-row sum of squares accumulated in smem across chunks; then
//   t = sigmoid(y0)*exp(scale)+1.1,  r = sqrt((t^2-1)/max(ssq,1e-8))
//   out = [t, y[,1:] * r]
// ----------------------------------------------------------------------------

#define THREADS 512
#define BM      128
#define KD      512
#define ND      512
#define KT      32
#define NITER   16          // KD / KT

// smem byte offsets
#define ASTG     (128 * 80)             // A tile stage: 128 rows x 80B (64B data + pad)
#define BSTG     (256 * 80)             // B tile stage
#define OFF_A    0
#define OFF_B    (2 * ASTG)             // 20480
#define OFF_Y0   (OFF_B + 2 * BSTG)     // 61440
#define Y0S      260                    // padded row stride in floats
#define OFF_BIAS (OFF_Y0 + 128 * Y0S * 4)   // 194560
#define OFF_PART (OFF_BIAS + ND * 4)        // 196608, float[4][128]
#define OFF_R    (OFF_PART + 4 * 128 * 4)   // 198656
#define OFF_T    (OFF_R + 128 * 4)
#define OFF_Y0V  (OFF_T + 128 * 4)
#define SMEM_TOTAL (OFF_Y0V + 128 * 4)      // 200192

__device__ __forceinline__ uint32_t smem_u32(const void* p) {
    uint32_t a;
    asm("{ .reg .u64 t; cvta.to.shared.u64 t, %1; cvt.u32.u64 %0, t; }"
        : "=r"(a) : "l"(p));
    return a;
}

__device__ __forceinline__ void ldm4(uint32_t r[4], uint32_t addr) {
    asm volatile("ldmatrix.sync.aligned.m8n8.x4.shared.b16 {%0,%1,%2,%3}, [%4];"
                 : "=r"(r[0]), "=r"(r[1]), "=r"(r[2]), "=r"(r[3]) : "r"(addr));
}

__device__ __forceinline__ void mma16816(float c[4], const uint32_t a[4],
                                         uint32_t b0, uint32_t b1) {
    asm volatile(
        "mma.sync.aligned.m16n8k16.row.col.f32.f16.f16.f32 "
        "{%0,%1,%2,%3}, {%4,%5,%6,%7}, {%8,%9}, {%0,%1,%2,%3};"
        : "+f"(c[0]), "+f"(c[1]), "+f"(c[2]), "+f"(c[3])
        : "r"(a[0]), "r"(a[1]), "r"(a[2]), "r"(a[3]), "r"(b0), "r"(b1));
}

__device__ __forceinline__ void ldg_cvt8(const float* p, uint32_t r[4]) {
    float4 v0 = *reinterpret_cast<const float4*>(p);
    float4 v1 = *reinterpret_cast<const float4*>(p + 4);
    __half2 h0 = __floats2half2_rn(v0.x, v0.y);
    __half2 h1 = __floats2half2_rn(v0.z, v0.w);
    __half2 h2 = __floats2half2_rn(v1.x, v1.y);
    __half2 h3 = __floats2half2_rn(v1.z, v1.w);
    r[0] = *reinterpret_cast<uint32_t*>(&h0);
    r[1] = *reinterpret_cast<uint32_t*>(&h1);
    r[2] = *reinterpret_cast<uint32_t*>(&h2);
    r[3] = *reinterpret_cast<uint32_t*>(&h3);
}

__global__ void __launch_bounds__(THREADS, 1)
lorentz_kernel(const float* __restrict__ x, const float* __restrict__ W,
               const float* __restrict__ bias, const float* __restrict__ scale,
               float* __restrict__ out) {
    extern __shared__ char smem[];
    const uint32_t sb = smem_u32(smem);
    const int tid  = threadIdx.x;
    const int lane = tid & 31;
    const int w    = tid >> 5;
    const int wm   = w >> 2;      // warp row 0..3 (32 rows each)
    const int wn   = w & 3;       // warp col 0..3 (64 cols each)
    const int row0 = blockIdx.x * BM;

    float* bias_sm = (float*)(smem + OFF_BIAS);
    float* part    = (float*)(smem + OFF_PART);   // [4][128]
    float* y0buf   = (float*)(smem + OFF_Y0);     // [128][Y0S]
    float* r_sm    = (float*)(smem + OFF_R);
    float* t_sm    = (float*)(smem + OFF_T);
    float* y0_sm   = (float*)(smem + OFF_Y0V);

    for (int i = tid; i < ND; i += THREADS) bias_sm[i] = bias[i];

    // ---- load/store addressing ----
    const int arow = tid >> 2, aseg = tid & 3;        // A: 512 units (row, 8-float seg)
    const float* aG = x + (size_t)(row0 + arow) * KD + aseg * 8;
    const int brow = tid >> 2, bseg = tid & 3;        // B: units tid and tid+512
    const float* bGa = W + (size_t)brow * KD + bseg * 8;
    const float* bGb = W + (size_t)(brow + 128) * KD + bseg * 8;

    char* aStsP  = smem + OFF_A + arow * 80 + aseg * 16;
    char* bStsP0 = smem + OFF_B + brow * 80 + bseg * 16;
    char* bStsP1 = bStsP0 + 128 * 80;

    const uint32_t aLdm = sb + OFF_A + (wm * 32 + (lane & 15)) * 80 + ((lane >> 4) << 4);
    const uint32_t bLdm = sb + OFF_B + (wn * 64 + (lane & 15)) * 80 + ((lane >> 4) << 4);

    uint32_t ah[4], bh0[4], bh1[4];
    float acc[2][8][4];

    __syncthreads();   // bias_sm visible before epilogue use (first pipe sync also covers)

    #pragma unroll 1
    for (int chunk = 0; chunk < 2; ++chunk) {
        const float* bB0 = bGa + (size_t)chunk * 256 * KD;
        const float* bB1 = bGb + (size_t)chunk * 256 * KD;

        #pragma unroll
        for (int m = 0; m < 2; ++m)
            #pragma unroll
            for (int f = 0; f < 8; ++f)
                #pragma unroll
                for (int k = 0; k < 4; ++k) acc[m][f][k] = 0.f;

        // ---- prologue ----
        ldg_cvt8(aG, ah); ldg_cvt8(bB0, bh0); ldg_cvt8(bB1, bh1);
        *(uint4*)(aStsP)  = *(uint4*)ah;
        *(uint4*)(bStsP0) = *(uint4*)bh0;
        *(uint4*)(bStsP1) = *(uint4*)bh1;
        ldg_cvt8(aG + KT, ah); ldg_cvt8(bB0 + KT, bh0); ldg_cvt8(bB1 + KT, bh1);
        __syncthreads();

        // ---- main K loop (double buffered) ----
        #pragma unroll 2
        for (int it = 0; it < NITER; ++it) {
            const int buf = it & 1;
            // compute from smem buf
            #pragma unroll
            for (int ks = 0; ks < 2; ++ks) {
                uint32_t a0[4], a1[4];
                ldm4(a0, aLdm + buf * ASTG + ks * 32);
                ldm4(a1, aLdm + buf * ASTG + 16 * 80 + ks * 32);
                #pragma unroll
                for (int g = 0; g < 4; ++g) {
                    uint32_t bb[4];
                    ldm4(bb, bLdm + buf * BSTG + g * (16 * 80) + ks * 32);
                    mma16816(acc[0][2 * g],     a0, bb[0], bb[2]);
                    mma16816(acc[0][2 * g + 1], a0, bb[1], bb[3]);
                    mma16816(acc[1][2 * g],     a1, bb[0], bb[2]);
                    mma16816(acc[1][2 * g + 1], a1, bb[1], bb[3]);
                }
            }
            if (it < NITER - 1) {
                const int nbuf = (it + 1) & 1;
                *(uint4*)(aStsP  + nbuf * ASTG) = *(uint4*)ah;
                *(uint4*)(bStsP0 + nbuf * BSTG) = *(uint4*)bh0;
                *(uint4*)(bStsP1 + nbuf * BSTG) = *(uint4*)bh1;
                __syncthreads();
                if (it < NITER - 2) {
                    const int k0 = (it + 2) * KT;
                    ldg_cvt8(aG + k0, ah);
                    ldg_cvt8(bB0 + k0, bh0);
                    ldg_cvt8(bB1 + k0, bh1);
                }
            }
        }

        // ---- per-chunk epilogue: bias add + row sum-of-squares ----
        float p[2][2] = {{0.f, 0.f}, {0.f, 0.f}};
        #pragma unroll
        for (int m = 0; m < 2; ++m) {
            #pragma unroll
            for (int f = 0; f < 8; ++f) {
                const int col = chunk * 256 + wn * 64 + f * 8 + (lane & 3) * 2;
                const float b0 = bias_sm[col], b1 = bias_sm[col + 1];
                acc[m][f][0] += b0; acc[m][f][1] += b1;
                acc[m][f][2] += b0; acc[m][f][3] += b1;
                p[m][0] += acc[m][f][0] * acc[m][f][0] + acc[m][f][1] * acc[m][f][1];
                p[m][1] += acc[m][f][2] * acc[m][f][2] + acc[m][f][3] * acc[m][f][3];
            }
        }
        if (chunk == 0 && wn == 0 && (lane & 3) == 0) {
            // this thread's reg0/reg2 of f==0 are global col 0: exclude + stash y0
            #pragma unroll
            for (int m = 0; m < 2; ++m) {
                p[m][0] -= acc[m][0][0] * acc[m][0][0];
                p[m][1] -= acc[m][0][2] * acc[m][0][2];
                y0_sm[wm * 32 + m * 16 + (lane >> 2)]     = acc[m][0][0];
                y0_sm[wm * 32 + m * 16 + 8 + (lane >> 2)] = acc[m][0][2];
            }
        }
        #pragma unroll
        for (int m = 0; m < 2; ++m)
            #pragma unroll
            for (int h = 0; h < 2; ++h) {
                float v = p[m][h];
                v += __shfl_xor_sync(0xffffffffu, v, 1);
                v += __shfl_xor_sync(0xffffffffu, v, 2);
                if ((lane & 3) == 0) {
                    const int r = wm * 32 + m * 16 + h * 8 + (lane >> 2);
                    if (chunk == 0) part[wn * 128 + r] = v;
                    else            part[wn * 128 + r] += v;
                }
            }

        if (chunk == 0) {
            // stash biased chunk-0 outputs to smem
            #pragma unroll
            for (int m = 0; m < 2; ++m) {
                const int rlo = wm * 32 + m * 16 + (lane >> 2);
                #pragma unroll
                for (int f = 0; f < 8; ++f) {
                    const int c = wn * 64 + f * 8 + (lane & 3) * 2;
                    y0buf[rlo * Y0S + c]           = acc[m][f][0];
                    y0buf[rlo * Y0S + c + 1]       = acc[m][f][1];
                    y0buf[(rlo + 8) * Y0S + c]     = acc[m][f][2];
                    y0buf[(rlo + 8) * Y0S + c + 1] = acc[m][f][3];
                }
            }
        }
    }

    __syncthreads();

    // ---- per-row scalars ----
    if (tid < 128) {
        const int r = tid;
        const float tot = part[r] + part[128 + r] + part[256 + r] + part[384 + r];
        const float y0 = y0_sm[r];
        const float es = expf(scale[0]);
        const float t  = es / (1.f + expf(-y0)) + 1.1f;
        const float rr = sqrtf((t * t - 1.f) / fmaxf(tot, 1e-8f));
        r_sm[r] = rr;
        t_sm[r] = t;
    }
    __syncthreads();

    // ---- write chunk 1 (cols 256..511) straight from registers ----
    #pragma unroll
    for (int m = 0; m < 2; ++m) {
        const int rlo = wm * 32 + m * 16 + (lane >> 2);
        const float rr0 = r_sm[rlo], rr1 = r_sm[rlo + 8];
        #pragma unroll
        for (int f = 0; f < 8; ++f) {
            const int c = 256 + wn * 64 + f * 8 + (lane & 3) * 2;
            float2 v0 = make_float2(acc[m][f][0] * rr0, acc[m][f][1] * rr0);
            float2 v1 = make_float2(acc[m][f][2] * rr1, acc[m][f][3] * rr1);
            *reinterpret_cast<float2*>(out + (size_t)(row0 + rlo) * ND + c)     = v0;
            *reinterpret_cast<float2*>(out + (size_t)(row0 + rlo + 8) * ND + c) = v1;
        }
    }

    // ---- write chunk 0 (cols 0..255) from smem, coalesced ----
    #pragma unroll
    for (int i = tid; i < 128 * 64; i += THREADS) {
        const int r  = i >> 6;
        const int c4 = (i & 63) * 4;
        const float rr = r_sm[r];
        float4 v;
        v.x = y0buf[r * Y0S + c4]     * rr;
        v.y = y0buf[r * Y0S + c4 + 1] * rr;
        v.z = y0buf[r * Y0S + c4 + 2] * rr;
        v.w = y0buf[r * Y0S + c4 + 3] * rr;
        if (c4 == 0) v.x = t_sm[r];
        *reinterpret_cast<float4*>(out + (size_t)(row0 + r) * ND + c4) = v;
    }
}

// ---------------- launch ----------------

extern "C" void kernel_launch(void* const* d_in, const int* in_sizes, int n_in,
                              void* d_out, int out_size) {
    const float* x     = (const float*)d_in[0];
    const float* W     = (const float*)d_in[1];
    const float* b     = (const float*)d_in[2];
    const float* scale = (const float*)d_in[3];
    float* out = (float*)d_out;

    const int rows = in_sizes[0] / KD;     // 65536
    const int grid = rows / BM;            // 512

    cudaFuncSetAttribute(lorentz_kernel,
                         cudaFuncAttributeMaxDynamicSharedMemorySize, SMEM_TOTAL);
    lorentz_kernel<<<grid, THREADS, SMEM_TOTAL>>>(x, W, b, scale, out);
}

// round 3
// speedup vs baseline: 1.0190x; 1.0190x over previous
#include <cuda_runtime.h>
#include <cuda_fp16.h>
#include <cstdint>
#include <math.h>

// ----------------------------------------------------------------------------
// LorentzLinear: fp16 mma.sync GEMM (fp32 accum) + fused Lorentz epilogue.
// CTA: 128 rows x 512 cols as two N-chunks of 256 (512 thr, warps 4x4).
// R3: register double-buffered ldmatrix frags (LDSM/HMMA overlap) and
//     chunk-0 stash moved smem -> gmem (write y, rescale in place at end).
// ----------------------------------------------------------------------------

#define THREADS 512
#define BM      128
#define KD      512
#define ND      512
#define KT      32
#define NITER   16          // KD / KT

// smem byte offsets
#define ASTG     (128 * 80)             // A stage: 128 rows x 80B (64B data + pad)
#define BSTG     (256 * 80)
#define OFF_A    0
#define OFF_B    (2 * ASTG)             // 20480
#define OFF_BIAS (OFF_B + 2 * BSTG)     // 61440
#define OFF_PART (OFF_BIAS + ND * 4)    // 63488  float[4][128]
#define OFF_R    (OFF_PART + 4 * 128 * 4)
#define OFF_T    (OFF_R + 128 * 4)
#define OFF_Y0V  (OFF_T + 128 * 4)
#define SMEM_TOTAL (OFF_Y0V + 128 * 4)  // ~67 KB

__device__ __forceinline__ uint32_t smem_u32(const void* p) {
    uint32_t a;
    asm("{ .reg .u64 t; cvta.to.shared.u64 t, %1; cvt.u32.u64 %0, t; }"
        : "=r"(a) : "l"(p));
    return a;
}

__device__ __forceinline__ void ldm4(uint32_t r[4], uint32_t addr) {
    asm volatile("ldmatrix.sync.aligned.m8n8.x4.shared.b16 {%0,%1,%2,%3}, [%4];"
                 : "=r"(r[0]), "=r"(r[1]), "=r"(r[2]), "=r"(r[3]) : "r"(addr));
}

__device__ __forceinline__ void mma16816(float c[4], const uint32_t a[4],
                                         uint32_t b0, uint32_t b1) {
    asm volatile(
        "mma.sync.aligned.m16n8k16.row.col.f32.f16.f16.f32 "
        "{%0,%1,%2,%3}, {%4,%5,%6,%7}, {%8,%9}, {%0,%1,%2,%3};"
        : "+f"(c[0]), "+f"(c[1]), "+f"(c[2]), "+f"(c[3])
        : "r"(a[0]), "r"(a[1]), "r"(a[2]), "r"(a[3]), "r"(b0), "r"(b1));
}

__device__ __forceinline__ void ldg_cvt8(const float* p, uint32_t r[4]) {
    float4 v0 = *reinterpret_cast<const float4*>(p);
    float4 v1 = *reinterpret_cast<const float4*>(p + 4);
    __half2 h0 = __floats2half2_rn(v0.x, v0.y);
    __half2 h1 = __floats2half2_rn(v0.z, v0.w);
    __half2 h2 = __floats2half2_rn(v1.x, v1.y);
    __half2 h3 = __floats2half2_rn(v1.z, v1.w);
    r[0] = *reinterpret_cast<uint32_t*>(&h0);
    r[1] = *reinterpret_cast<uint32_t*>(&h1);
    r[2] = *reinterpret_cast<uint32_t*>(&h2);
    r[3] = *reinterpret_cast<uint32_t*>(&h3);
}

__global__ void __launch_bounds__(THREADS, 1)
lorentz_kernel(const float* __restrict__ x, const float* __restrict__ W,
               const float* __restrict__ bias, const float* __restrict__ scale,
               float* __restrict__ out) {
    extern __shared__ char smem[];
    const uint32_t sb = smem_u32(smem);
    const int tid  = threadIdx.x;
    const int lane = tid & 31;
    const int w    = tid >> 5;
    const int wm   = w >> 2;      // warp row 0..3 (32 rows)
    const int wn   = w & 3;       // warp col 0..3 (64 cols)
    const int row0 = blockIdx.x * BM;

    float* bias_sm = (float*)(smem + OFF_BIAS);
    float* part    = (float*)(smem + OFF_PART);   // [4][128]
    float* r_sm    = (float*)(smem + OFF_R);
    float* t_sm    = (float*)(smem + OFF_T);
    float* y0_sm   = (float*)(smem + OFF_Y0V);

    for (int i = tid; i < ND; i += THREADS) bias_sm[i] = bias[i];

    // ---- load/store addressing ----
    const int arow = tid >> 2, aseg = tid & 3;
    const float* aG = x + (size_t)(row0 + arow) * KD + aseg * 8;
    const float* bGa = W + (size_t)arow * KD + aseg * 8;
    const float* bGb = W + (size_t)(arow + 128) * KD + aseg * 8;

    char* aStsP  = smem + OFF_A + arow * 80 + aseg * 16;
    char* bStsP0 = smem + OFF_B + arow * 80 + aseg * 16;
    char* bStsP1 = bStsP0 + 128 * 80;

    const uint32_t aLdm = sb + OFF_A + (wm * 32 + (lane & 15)) * 80 + ((lane >> 4) << 4);
    const uint32_t bLdm = sb + OFF_B + (wn * 64 + (lane & 15)) * 80 + ((lane >> 4) << 4);

    uint32_t ah[4], bh0[4], bh1[4];
    float acc[2][8][4];

    __syncthreads();

    #pragma unroll 1
    for (int chunk = 0; chunk < 2; ++chunk) {
        const float* bB0 = bGa + (size_t)chunk * 256 * KD;
        const float* bB1 = bGb + (size_t)chunk * 256 * KD;

        #pragma unroll
        for (int m = 0; m < 2; ++m)
            #pragma unroll
            for (int f = 0; f < 8; ++f)
                #pragma unroll
                for (int k = 0; k < 4; ++k) acc[m][f][k] = 0.f;

        // ---- prologue ----
        ldg_cvt8(aG, ah); ldg_cvt8(bB0, bh0); ldg_cvt8(bB1, bh1);
        *(uint4*)(aStsP)  = *(uint4*)ah;
        *(uint4*)(bStsP0) = *(uint4*)bh0;
        *(uint4*)(bStsP1) = *(uint4*)bh1;
        ldg_cvt8(aG + KT, ah); ldg_cvt8(bB0 + KT, bh0); ldg_cvt8(bB1 + KT, bh1);
        __syncthreads();

        // ---- main K loop: smem double buffer + register frag double buffer ----
        #pragma unroll 2
        for (int it = 0; it < NITER; ++it) {
            const int buf = it & 1;
            const uint32_t aB = aLdm + buf * ASTG;
            const uint32_t bB = bLdm + buf * BSTG;

            uint32_t afr[2][2][4];   // [ks][rowblk][4]
            uint32_t bfr[2][4];      // parity double buffer

            ldm4(afr[0][0], aB);
            ldm4(afr[0][1], aB + 16 * 80);
            ldm4(bfr[0],    bB);

            #pragma unroll
            for (int ks = 0; ks < 2; ++ks) {
                #pragma unroll
                for (int g = 0; g < 4; ++g) {
                    const int cur = (ks * 4 + g) & 1, nxt = cur ^ 1;
                    if (g < 3) {
                        ldm4(bfr[nxt], bB + (g + 1) * (16 * 80) + ks * 32);
                    } else if (ks == 0) {
                        ldm4(bfr[nxt], bB + 32);
                        ldm4(afr[1][0], aB + 32);
                        ldm4(afr[1][1], aB + 16 * 80 + 32);
                    }
                    mma16816(acc[0][2 * g],     afr[ks][0], bfr[cur][0], bfr[cur][2]);
                    mma16816(acc[0][2 * g + 1], afr[ks][0], bfr[cur][1], bfr[cur][3]);
                    mma16816(acc[1][2 * g],     afr[ks][1], bfr[cur][0], bfr[cur][2]);
                    mma16816(acc[1][2 * g + 1], afr[ks][1], bfr[cur][1], bfr[cur][3]);
                }
            }

            if (it < NITER - 1) {
                const int nbuf = (it + 1) & 1;
                *(uint4*)(aStsP  + nbuf * ASTG) = *(uint4*)ah;
                *(uint4*)(bStsP0 + nbuf * BSTG) = *(uint4*)bh0;
                *(uint4*)(bStsP1 + nbuf * BSTG) = *(uint4*)bh1;
                __syncthreads();
                if (it < NITER - 2) {
                    const int k0 = (it + 2) * KT;
                    ldg_cvt8(aG + k0, ah);
                    ldg_cvt8(bB0 + k0, bh0);
                    ldg_cvt8(bB1 + k0, bh1);
                }
            }
        }

        // ---- per-chunk epilogue: bias + row sum-of-squares (+ y stash to gmem) ----
        float p[2][2] = {{0.f, 0.f}, {0.f, 0.f}};
        #pragma unroll
        for (int m = 0; m < 2; ++m) {
            #pragma unroll
            for (int f = 0; f < 8; ++f) {
                const int col = chunk * 256 + wn * 64 + f * 8 + (lane & 3) * 2;
                const float b0 = bias_sm[col], b1 = bias_sm[col + 1];
                acc[m][f][0] += b0; acc[m][f][1] += b1;
                acc[m][f][2] += b0; acc[m][f][3] += b1;
                p[m][0] += acc[m][f][0] * acc[m][f][0] + acc[m][f][1] * acc[m][f][1];
                p[m][1] += acc[m][f][2] * acc[m][f][2] + acc[m][f][3] * acc[m][f][3];
            }
        }
        if (chunk == 0 && wn == 0 && (lane & 3) == 0) {
            #pragma unroll
            for (int m = 0; m < 2; ++m) {
                p[m][0] -= acc[m][0][0] * acc[m][0][0];
                p[m][1] -= acc[m][0][2] * acc[m][0][2];
                y0_sm[wm * 32 + m * 16 + (lane >> 2)]     = acc[m][0][0];
                y0_sm[wm * 32 + m * 16 + 8 + (lane >> 2)] = acc[m][0][2];
            }
        }
        #pragma unroll
        for (int m = 0; m < 2; ++m)
            #pragma unroll
            for (int h = 0; h < 2; ++h) {
                float v = p[m][h];
                v += __shfl_xor_sync(0xffffffffu, v, 1);
                v += __shfl_xor_sync(0xffffffffu, v, 2);
                if ((lane & 3) == 0) {
                    const int r = wm * 32 + m * 16 + h * 8 + (lane >> 2);
                    if (chunk == 0) part[wn * 128 + r] = v;
                    else            part[wn * 128 + r] += v;
                }
            }

        if (chunk == 0) {
            // stash biased (unscaled) chunk-0 y straight to gmem; rescaled later
            #pragma unroll
            for (int m = 0; m < 2; ++m) {
                const int rlo = wm * 32 + m * 16 + (lane >> 2);
                #pragma unroll
                for (int f = 0; f < 8; ++f) {
                    const int c = wn * 64 + f * 8 + (lane & 3) * 2;
                    *reinterpret_cast<float2*>(out + (size_t)(row0 + rlo) * ND + c) =
                        make_float2(acc[m][f][0], acc[m][f][1]);
                    *reinterpret_cast<float2*>(out + (size_t)(row0 + rlo + 8) * ND + c) =
                        make_float2(acc[m][f][2], acc[m][f][3]);
                }
            }
        }
    }

    __syncthreads();

    // ---- per-row scalars ----
    if (tid < 128) {
        const int r = tid;
        const float tot = part[r] + part[128 + r] + part[256 + r] + part[384 + r];
        const float y0 = y0_sm[r];
        const float es = expf(scale[0]);
        const float t  = es / (1.f + expf(-y0)) + 1.1f;
        const float rr = sqrtf((t * t - 1.f) / fmaxf(tot, 1e-8f));
        r_sm[r] = rr;
        t_sm[r] = t;
    }
    __syncthreads();

    // ---- write chunk 1 (cols 256..511) from registers, scaled ----
    #pragma unroll
    for (int m = 0; m < 2; ++m) {
        const int rlo = wm * 32 + m * 16 + (lane >> 2);
        const float rr0 = r_sm[rlo], rr1 = r_sm[rlo + 8];
        #pragma unroll
        for (int f = 0; f < 8; ++f) {
            const int c = 256 + wn * 64 + f * 8 + (lane & 3) * 2;
            *reinterpret_cast<float2*>(out + (size_t)(row0 + rlo) * ND + c) =
                make_float2(acc[m][f][0] * rr0, acc[m][f][1] * rr0);
            *reinterpret_cast<float2*>(out + (size_t)(row0 + rlo + 8) * ND + c) =
                make_float2(acc[m][f][2] * rr1, acc[m][f][3] * rr1);
        }
    }

    // ---- rescale chunk 0 (cols 0..255) in place (L2-hot) ----
    #pragma unroll 4
    for (int i = tid; i < 128 * 64; i += THREADS) {
        const int r  = i >> 6;
        const int c4 = (i & 63) * 4;
        const float rr = r_sm[r];
        float* p4 = out + (size_t)(row0 + r) * ND + c4;
        float4 v = *reinterpret_cast<float4*>(p4);
        v.x *= rr; v.y *= rr; v.z *= rr; v.w *= rr;
        if (c4 == 0) v.x = t_sm[r];
        *reinterpret_cast<float4*>(p4) = v;
    }
}

// ---------------- launch ----------------

extern "C" void kernel_launch(void* const* d_in, const int* in_sizes, int n_in,
                              void* d_out, int out_size) {
    const float* x     = (const float*)d_in[0];
    const float* W     = (const float*)d_in[1];
    const float* b     = (const float*)d_in[2];
    const float* scale = (const float*)d_in[3];
    float* out = (float*)d_out;

    const int rows = in_sizes[0] / KD;     // 65536
    const int grid = rows / BM;            // 512

    cudaFuncSetAttribute(lorentz_kernel,
                         cudaFuncAttributeMaxDynamicSharedMemorySize, SMEM_TOTAL);
    lorentz_kernel<<<grid, THREADS, SMEM_TOTAL>>>(x, W, b, scale, out);
}

// round 5
// speedup vs baseline: 1.2566x; 1.2331x over previous
#include <cuda_runtime.h>
#include <cuda_fp16.h>
#include <cstdint>
#include <math.h>

// ----------------------------------------------------------------------------
// LorentzLinear. Two kernels:
//  A) convert x (65536x512 f32) and W (512x512 f32) to fp16 scratch.
//  B) fp16 mma.sync GEMM with cp.async 3-stage pipeline + fused epilogue.
// CTA: 128 rows x 512 cols as two N-chunks of 256. 512 threads, warps 4x4.
// ----------------------------------------------------------------------------

#define THREADS 512
#define BM      128
#define KD      512
#define ND      512
#define KT      64
#define NITER   8           // KD / KT per chunk
#define NST     3           // pipeline stages
#define NROWS   65536

__device__ __half g_xh[(size_t)NROWS * KD];
__device__ __half g_wh[ND * KD];

#define ROWB    144                      // 128B data + 16B pad
#define AST     (128 * ROWB)
#define BST     (256 * ROWB)
#define STG     (AST + BST)              // 55296
#define OFF_A   0
#define OFF_B   AST
#define OFF_BIAS (NST * STG)             // 165888
#define OFF_PART (OFF_BIAS + ND * 4)
#define OFF_R    (OFF_PART + 4 * 128 * 4)
#define OFF_T    (OFF_R + 128 * 4)
#define OFF_Y0V  (OFF_T + 128 * 4)
#define SMEM_TOTAL (OFF_Y0V + 128 * 4)

__device__ __forceinline__ uint32_t smem_u32(const void* p) {
    uint32_t a;
    asm("{ .reg .u64 t; cvta.to.shared.u64 t, %1; cvt.u32.u64 %0, t; }"
        : "=r"(a) : "l"(p));
    return a;
}

__device__ __forceinline__ void ldm4(uint32_t r[4], uint32_t addr) {
    asm volatile("ldmatrix.sync.aligned.m8n8.x4.shared.b16 {%0,%1,%2,%3}, [%4];"
                 : "=r"(r[0]), "=r"(r[1]), "=r"(r[2]), "=r"(r[3]) : "r"(addr));
}

__device__ __forceinline__ void mma16816(float c[4], const uint32_t a[4],
                                         uint32_t b0, uint32_t b1) {
    asm volatile(
        "mma.sync.aligned.m16n8k16.row.col.f32.f16.f16.f32 "
        "{%0,%1,%2,%3}, {%4,%5,%6,%7}, {%8,%9}, {%0,%1,%2,%3};"
        : "+f"(c[0]), "+f"(c[1]), "+f"(c[2]), "+f"(c[3])
        : "r"(a[0]), "r"(a[1]), "r"(a[2]), "r"(a[3]), "r"(b0), "r"(b1));
}

__device__ __forceinline__ void cp16(uint32_t smem_dst, const void* gsrc) {
    asm volatile("cp.async.cg.shared.global [%0], [%1], 16;"
                 :: "r"(smem_dst), "l"(gsrc));
}
#define CP_COMMIT() asm volatile("cp.async.commit_group;" ::: "memory")
#define CP_WAIT1()  asm volatile("cp.async.wait_group 1;" ::: "memory")

// ---------------- kernel A: f32 -> f16 convert ----------------

__global__ void __launch_bounds__(256)
cvt_kernel(const float* __restrict__ x, const float* __restrict__ W) {
    const size_t NX8 = (size_t)NROWS * KD / 8;
    const size_t NW8 = (size_t)ND * KD / 8;
    size_t u = (size_t)blockIdx.x * blockDim.x + threadIdx.x;
    const float* src;
    __half* dst;
    if (u < NX8)            { src = x + u * 8;           dst = g_xh + u * 8; }
    else if (u < NX8 + NW8) { size_t v = u - NX8; src = W + v * 8; dst = g_wh + v * 8; }
    else return;
    float4 v0 = *reinterpret_cast<const float4*>(src);
    float4 v1 = *reinterpret_cast<const float4*>(src + 4);
    __half2 h[4];
    h[0] = __floats2half2_rn(v0.x, v0.y);
    h[1] = __floats2half2_rn(v0.z, v0.w);
    h[2] = __floats2half2_rn(v1.x, v1.y);
    h[3] = __floats2half2_rn(v1.z, v1.w);
    *reinterpret_cast<uint4*>(dst) = *reinterpret_cast<uint4*>(h);
}

// ---------------- kernel B: GEMM + Lorentz epilogue ----------------

__global__ void __launch_bounds__(THREADS, 1)
lorentz_kernel(const float* __restrict__ bias, const float* __restrict__ scale,
               float* __restrict__ out) {
    extern __shared__ char smem[];
    const uint32_t sb = smem_u32(smem);
    const int tid  = threadIdx.x;
    const int lane = tid & 31;
    const int w    = tid >> 5;
    const int wm   = w >> 2;
    const int wn   = w & 3;
    const int row0 = blockIdx.x * BM;

    float* bias_sm = (float*)(smem + OFF_BIAS);
    float* part    = (float*)(smem + OFF_PART);
    float* r_sm    = (float*)(smem + OFF_R);
    float* t_sm    = (float*)(smem + OFF_T);
    float* y0_sm   = (float*)(smem + OFF_Y0V);

    for (int i = tid; i < ND; i += THREADS) bias_sm[i] = bias[i];

    // cp.async addressing: 16B units. A tile 1024 units (2/thread),
    // B tile 2048 units (4/thread). row = unit>>3, seg = unit&7.
    const int urow = tid >> 3, useg = tid & 7;
    const __half* aG0 = g_xh + (size_t)(row0 + urow) * KD + useg * 8;
    const __half* aG1 = g_xh + (size_t)(row0 + urow + 64) * KD + useg * 8;
    const uint32_t aD0 = sb + OFF_A + urow * ROWB + useg * 16;
    const uint32_t aD1 = aD0 + 64 * ROWB;
    const uint32_t bD  = sb + OFF_B + urow * ROWB + useg * 16;

    const uint32_t aLdm = sb + OFF_A + (wm * 32 + (lane & 15)) * ROWB + ((lane >> 4) << 4);
    const uint32_t bLdm = sb + OFF_B + (wn * 64 + (lane & 15)) * ROWB + ((lane >> 4) << 4);

    float acc[2][8][4];

    __syncthreads();

    #pragma unroll 1
    for (int chunk = 0; chunk < 2; ++chunk) {
        const __half* wBase = g_wh + (size_t)chunk * 256 * KD + useg * 8;

        #pragma unroll
        for (int m = 0; m < 2; ++m)
            #pragma unroll
            for (int f = 0; f < 8; ++f)
                #pragma unroll
                for (int k = 0; k < 4; ++k) acc[m][f][k] = 0.f;

        __syncthreads();   // stages free before chunk prologue overwrites

        #define ISSUE(J) do {                                              \
            const int _j = (J);                                            \
            if (_j < NITER) {                                              \
                const int _st = _j % NST;                                  \
                const int _k0 = _j * KT;                                   \
                cp16(aD0 + _st * STG, aG0 + _k0);                          \
                cp16(aD1 + _st * STG, aG1 + _k0);                          \
                _Pragma("unroll")                                          \
                for (int _jj = 0; _jj < 4; ++_jj)                          \
                    cp16(bD + _st * STG + _jj * (64 * ROWB),               \
                         wBase + (size_t)(urow + _jj * 64) * KD + _k0);    \
            }                                                              \
            CP_COMMIT();                                                   \
        } while (0)

        ISSUE(0);
        ISSUE(1);

        #pragma unroll 1
        for (int it = 0; it < NITER; ++it) {
            const int st = it % NST;
            CP_WAIT1();
            __syncthreads();
            ISSUE(it + 2);

            const uint32_t aB = aLdm + st * STG;
            const uint32_t bB = bLdm + st * STG;
            #pragma unroll
            for (int ks = 0; ks < 4; ++ks) {
                uint32_t a0[4], a1[4];
                ldm4(a0, aB + ks * 32);
                ldm4(a1, aB + 16 * ROWB + ks * 32);
                #pragma unroll
                for (int g = 0; g < 4; ++g) {
                    uint32_t bb[4];
                    ldm4(bb, bB + g * (16 * ROWB) + ks * 32);
                    mma16816(acc[0][2 * g],     a0, bb[0], bb[2]);
                    mma16816(acc[0][2 * g + 1], a0, bb[1], bb[3]);
                    mma16816(acc[1][2 * g],     a1, bb[0], bb[2]);
                    mma16816(acc[1][2 * g + 1], a1, bb[1], bb[3]);
                }
            }
            __syncthreads();   // stage consumed before overwrite
        }
        #undef ISSUE

        // ---- per-chunk epilogue: bias + row sum-of-squares ----
        float p[2][2] = {{0.f, 0.f}, {0.f, 0.f}};
        #pragma unroll
        for (int m = 0; m < 2; ++m) {
            #pragma unroll
            for (int f = 0; f < 8; ++f) {
                const int col = chunk * 256 + wn * 64 + f * 8 + (lane & 3) * 2;
                const float b0 = bias_sm[col], b1 = bias_sm[col + 1];
                acc[m][f][0] += b0; acc[m][f][1] += b1;
                acc[m][f][2] += b0; acc[m][f][3] += b1;
                p[m][0] += acc[m][f][0] * acc[m][f][0] + acc[m][f][1] * acc[m][f][1];
                p[m][1] += acc[m][f][2] * acc[m][f][2] + acc[m][f][3] * acc[m][f][3];
            }
        }
        if (chunk == 0 && wn == 0 && (lane & 3) == 0) {
            #pragma unroll
            for (int m = 0; m < 2; ++m) {
                p[m][0] -= acc[m][0][0] * acc[m][0][0];
                p[m][1] -= acc[m][0][2] * acc[m][0][2];
                y0_sm[wm * 32 + m * 16 + (lane >> 2)]     = acc[m][0][0];
                y0_sm[wm * 32 + m * 16 + 8 + (lane >> 2)] = acc[m][0][2];
            }
        }
        #pragma unroll
        for (int m = 0; m < 2; ++m)
            #pragma unroll
            for (int h = 0; h < 2; ++h) {
                float v = p[m][h];
                v += __shfl_xor_sync(0xffffffffu, v, 1);
                v += __shfl_xor_sync(0xffffffffu, v, 2);
                if ((lane & 3) == 0) {
                    const int r = wm * 32 + m * 16 + h * 8 + (lane >> 2);
                    if (chunk == 0) part[wn * 128 + r] = v;
                    else            part[wn * 128 + r] += v;
                }
            }

        if (chunk == 0) {
            #pragma unroll
            for (int m = 0; m < 2; ++m) {
                const int rlo = wm * 32 + m * 16 + (lane >> 2);
                #pragma unroll
                for (int f = 0; f < 8; ++f) {
                    const int c = wn * 64 + f * 8 + (lane & 3) * 2;
                    *reinterpret_cast<float2*>(out + (size_t)(row0 + rlo) * ND + c) =
                        make_float2(acc[m][f][0], acc[m][f][1]);
                    *reinterpret_cast<float2*>(out + (size_t)(row0 + rlo + 8) * ND + c) =
                        make_float2(acc[m][f][2], acc[m][f][3]);
                }
            }
        }
    }

    __syncthreads();

    if (tid < 128) {
        const int r = tid;
        const float tot = part[r] + part[128 + r] + part[256 + r] + part[384 + r];
        const float y0 = y0_sm[r];
        const float es = expf(scale[0]);
        const float t  = es / (1.f + expf(-y0)) + 1.1f;
        const float rr = sqrtf((t * t - 1.f) / fmaxf(tot, 1e-8f));
        r_sm[r] = rr;
        t_sm[r] = t;
    }
    __syncthreads();

    #pragma unroll
    for (int m = 0; m < 2; ++m) {
        const int rlo = wm * 32 + m * 16 + (lane >> 2);
        const float rr0 = r_sm[rlo], rr1 = r_sm[rlo + 8];
        #pragma unroll
        for (int f = 0; f < 8; ++f) {
            const int c = 256 + wn * 64 + f * 8 + (lane & 3) * 2;
            *reinterpret_cast<float2*>(out + (size_t)(row0 + rlo) * ND + c) =
                make_float2(acc[m][f][0] * rr0, acc[m][f][1] * rr0);
            *reinterpret_cast<float2*>(out + (size_t)(row0 + rlo + 8) * ND + c) =
                make_float2(acc[m][f][2] * rr1, acc[m][f][3] * rr1);
        }
    }

    #pragma unroll 4
    for (int i = tid; i < 128 * 64; i += THREADS) {
        const int r  = i >> 6;
        const int c4 = (i & 63) * 4;
        const float rr = r_sm[r];
        float* p4 = out + (size_t)(row0 + r) * ND + c4;
        float4 v = *reinterpret_cast<float4*>(p4);
        v.x *= rr; v.y *= rr; v.z *= rr; v.w *= rr;
        if (c4 == 0) v.x = t_sm[r];
        *reinterpret_cast<float4*>(p4) = v;
    }
}

// ---------------- launch ----------------

extern "C" void kernel_launch(void* const* d_in, const int* in_sizes, int n_in,
                              void* d_out, int out_size) {
    const float* x     = (const float*)d_in[0];
    const float* W     = (const float*)d_in[1];
    const float* b     = (const float*)d_in[2];
    const float* scale = (const float*)d_in[3];
    float* out = (float*)d_out;

    const size_t total_units = (size_t)NROWS * KD / 8 + (size_t)ND * KD / 8;
    const int cvt_blocks = (int)((total_units + 255) / 256);
    cvt_kernel<<<cvt_blocks, 256>>>(x, W);

    const int rows = in_sizes[0] / KD;     // 65536
    const int grid = rows / BM;            // 512
    cudaFuncSetAttribute(lorentz_kernel,
                         cudaFuncAttributeMaxDynamicSharedMemorySize, SMEM_TOTAL);
    lorentz_kernel<<<grid, THREADS, SMEM_TOTAL>>>(b, scale, out);
}

// round 6
// speedup vs baseline: 1.3326x; 1.0605x over previous
#include <cuda_runtime.h>
#include <cuda_fp16.h>
#include <cstdint>
#include <math.h>

// ----------------------------------------------------------------------------
// LorentzLinear R6:
//  - tiny kernel converts W (512x512 f32) -> fp16 scratch
//  - main kernel: per-CTA A panel (128 rows x 512) converted f32->fp16 into
//    resident smem once; flat 16-iteration B-only cp.async pipeline (3 stages,
//    1 syncthreads/iter, no drain across the two N-chunks); fp16 mma.sync;
//    fused Lorentz epilogue (chunk-0 epilogue inline at iteration 7).
//  - XOR-swizzled smem (cu ^ (row&7) on 16B units): zero padding waste.
// ----------------------------------------------------------------------------

#define THREADS 512
#define BM      128
#define KD      512
#define ND      512
#define KT      64          // halves per B k-tile
#define NTOT    16          // 2 chunks x 8 k-tiles, flat
#define NST     3
#define NROWS   65536

__device__ __half g_wh[ND * KD];

// smem layout (bytes)
#define OFF_APAN 0
#define APAN_SZ  (128 * 1024)            // 128 rows x 512 fp16, swizzled
#define OFF_B    APAN_SZ                 // 131072
#define BST      32768                   // 256 rows x 64 fp16 (128B rows), swizzled
#define OFF_PART (OFF_B + NST * BST)     // 229376
#define OFF_Y0V  (OFF_PART + 512)
#define OFF_R    (OFF_Y0V + 512)
#define OFF_T    (OFF_R + 512)
#define SMEM_TOTAL (OFF_T + 512)         // 231424

__device__ __forceinline__ uint32_t smem_u32(const void* p) {
    uint32_t a;
    asm("{ .reg .u64 t; cvta.to.shared.u64 t, %1; cvt.u32.u64 %0, t; }"
        : "=r"(a) : "l"(p));
    return a;
}

__device__ __forceinline__ void ldm4(uint32_t r[4], uint32_t addr) {
    asm volatile("ldmatrix.sync.aligned.m8n8.x4.shared.b16 {%0,%1,%2,%3}, [%4];"
                 : "=r"(r[0]), "=r"(r[1]), "=r"(r[2]), "=r"(r[3]) : "r"(addr));
}

__device__ __forceinline__ void mma16816(float c[4], const uint32_t a[4],
                                         uint32_t b0, uint32_t b1) {
    asm volatile(
        "mma.sync.aligned.m16n8k16.row.col.f32.f16.f16.f32 "
        "{%0,%1,%2,%3}, {%4,%5,%6,%7}, {%8,%9}, {%0,%1,%2,%3};"
        : "+f"(c[0]), "+f"(c[1]), "+f"(c[2]), "+f"(c[3])
        : "r"(a[0]), "r"(a[1]), "r"(a[2]), "r"(a[3]), "r"(b0), "r"(b1));
}

__device__ __forceinline__ void cp16(uint32_t smem_dst, const void* gsrc) {
    asm volatile("cp.async.cg.shared.global [%0], [%1], 16;"
                 :: "r"(smem_dst), "l"(gsrc));
}
#define CP_COMMIT() asm volatile("cp.async.commit_group;" ::: "memory")
#define CP_WAIT1()  asm volatile("cp.async.wait_group 1;" ::: "memory")

__device__ __forceinline__ void sts128(uint32_t addr, uint32_t r0, uint32_t r1,
                                       uint32_t r2, uint32_t r3) {
    asm volatile("st.shared.v4.b32 [%0], {%1,%2,%3,%4};"
                 :: "r"(addr), "r"(r0), "r"(r1), "r"(r2), "r"(r3) : "memory");
}

// ---------------- kernel A: W f32 -> f16 ----------------

__global__ void __launch_bounds__(256)
cvtW_kernel(const float* __restrict__ W) {
    const size_t u = (size_t)blockIdx.x * 256 + threadIdx.x;   // 8 elems each
    if (u >= (size_t)ND * KD / 8) return;
    const float* src = W + u * 8;
    float4 v0 = *reinterpret_cast<const float4*>(src);
    float4 v1 = *reinterpret_cast<const float4*>(src + 4);
    __half2 h[4];
    h[0] = __floats2half2_rn(v0.x, v0.y);
    h[1] = __floats2half2_rn(v0.z, v0.w);
    h[2] = __floats2half2_rn(v1.x, v1.y);
    h[3] = __floats2half2_rn(v1.z, v1.w);
    *reinterpret_cast<uint4*>(g_wh + u * 8) = *reinterpret_cast<uint4*>(h);
}

// ---------------- main kernel ----------------

__global__ void __launch_bounds__(THREADS, 1)
lorentz_kernel(const float* __restrict__ x, const float* __restrict__ bias,
               const float* __restrict__ scale, float* __restrict__ out) {
    extern __shared__ char smem[];
    const uint32_t sb = smem_u32(smem);
    const int tid  = threadIdx.x;
    const int lane = tid & 31;
    const int w    = tid >> 5;
    const int wm   = w >> 2;          // warp row group (32 rows)
    const int wn   = w & 3;           // warp col group (64 cols)
    const int lo   = lane & 7;        // swizzle key (== row&7 for ldmatrix rows)
    const int hi   = lane >> 4;
    const int row0 = blockIdx.x * BM;

    float* part  = (float*)(smem + OFF_PART);   // [128] atomic partial ssq
    float* y0_sm = (float*)(smem + OFF_Y0V);
    float* r_sm  = (float*)(smem + OFF_R);
    float* t_sm  = (float*)(smem + OFF_T);

    if (tid < 128) part[tid] = 0.f;

    // ---- B cp.async addressing: 2048 16B units / 512 thr = 4 per thread ----
    const int burow = tid >> 3, bcu = tid & 7;
    const uint32_t bDst0 = sb + OFF_B + burow * 128 + ((bcu ^ (burow & 7)) << 4);
    const __half* wSrc0 = g_wh + (size_t)burow * KD + bcu * 8;

    #define ISSUE(J) do {                                                     \
        const int _j = (J);                                                   \
        if (_j < NTOT) {                                                      \
            const int _st = _j % NST;                                         \
            const __half* _src = wSrc0 + (size_t)(_j >> 3) * 256 * KD         \
                                       + (_j & 7) * KT;                       \
            _Pragma("unroll")                                                 \
            for (int _jj = 0; _jj < 4; ++_jj)                                 \
                cp16(bDst0 + _st * BST + _jj * 8192,                          \
                     _src + (size_t)_jj * 64 * KD);                           \
        }                                                                     \
        CP_COMMIT();                                                          \
    } while (0)

    ISSUE(0);
    ISSUE(1);

    // ---- A panel: convert this CTA's 128x512 f32 rows to fp16 smem ----
    // 8192 16B-units, 16 per thread; unit = 8 fp16 = 8 f32 (32B) input.
    #pragma unroll
    for (int i = 0; i < 16; ++i) {
        const int u   = tid + i * THREADS;
        const int row = u >> 6, cu = u & 63;
        const float* src = x + (size_t)(row0 + row) * KD + cu * 8;
        float4 v0 = *reinterpret_cast<const float4*>(src);
        float4 v1 = *reinterpret_cast<const float4*>(src + 4);
        __half2 h0 = __floats2half2_rn(v0.x, v0.y);
        __half2 h1 = __floats2half2_rn(v0.z, v0.w);
        __half2 h2 = __floats2half2_rn(v1.x, v1.y);
        __half2 h3 = __floats2half2_rn(v1.z, v1.w);
        const uint32_t dst = sb + OFF_APAN + row * 1024 + ((cu ^ (row & 7)) << 4);
        sts128(dst, *(uint32_t*)&h0, *(uint32_t*)&h1,
                    *(uint32_t*)&h2, *(uint32_t*)&h3);
    }
    __syncthreads();

    // ---- ldmatrix bases ----
    const uint32_t aBase = sb + OFF_APAN + (wm * 32 + (lane & 15)) * 1024;
    const uint32_t bBase = sb + OFF_B + (wn * 64 + (lane & 15)) * 128;

    float acc[2][8][4];
    #pragma unroll
    for (int m = 0; m < 2; ++m)
        #pragma unroll
        for (int f = 0; f < 8; ++f)
            #pragma unroll
            for (int k = 0; k < 4; ++k) acc[m][f][k] = 0.f;

    float y0r[2] = {0.f, 0.f};   // col-0 y values (wn==0, lane&3==0 threads)

    // ---- flat mainloop: 16 k-tile iterations across both N-chunks ----
    #pragma unroll 1
    for (int j = 0; j < NTOT; ++j) {
        const int st = j % NST;
        CP_WAIT1();
        __syncthreads();
        ISSUE(j + 2);

        const uint32_t bS = bBase + st * BST;
        #pragma unroll
        for (int ks = 0; ks < 4; ++ks) {
            const int s = (j & 7) * 4 + ks;           // global k16 index 0..31
            const uint32_t axo = (uint32_t)(((s * 2 + hi) ^ lo) << 4);
            uint32_t a0[4], a1[4];
            ldm4(a0, aBase + axo);
            ldm4(a1, aBase + 16 * 1024 + axo);
            const uint32_t bxo = (uint32_t)((((ks * 2 + hi) ^ lo)) << 4);
            #pragma unroll
            for (int g = 0; g < 4; ++g) {
                uint32_t bb[4];
                ldm4(bb, bS + g * 2048 + bxo);
                mma16816(acc[0][2 * g],     a0, bb[0], bb[2]);
                mma16816(acc[0][2 * g + 1], a0, bb[1], bb[3]);
                mma16816(acc[1][2 * g],     a1, bb[0], bb[2]);
                mma16816(acc[1][2 * g + 1], a1, bb[1], bb[3]);
            }
        }

        if (j == 7) {
            // ---- chunk-0 epilogue (cols 0..255): bias, ssq, stash, reset ----
            float p[2][2] = {{0.f, 0.f}, {0.f, 0.f}};
            #pragma unroll
            for (int m = 0; m < 2; ++m) {
                #pragma unroll
                for (int f = 0; f < 8; ++f) {
                    const int col = wn * 64 + f * 8 + (lane & 3) * 2;
                    const float2 bv = __ldg(reinterpret_cast<const float2*>(bias + col));
                    acc[m][f][0] += bv.x; acc[m][f][1] += bv.y;
                    acc[m][f][2] += bv.x; acc[m][f][3] += bv.y;
                    p[m][0] += acc[m][f][0] * acc[m][f][0] + acc[m][f][1] * acc[m][f][1];
                    p[m][1] += acc[m][f][2] * acc[m][f][2] + acc[m][f][3] * acc[m][f][3];
                }
            }
            if (wn == 0 && (lane & 3) == 0) {
                #pragma unroll
                for (int m = 0; m < 2; ++m) {
                    p[m][0] -= acc[m][0][0] * acc[m][0][0];
                    p[m][1] -= acc[m][0][2] * acc[m][0][2];
                    y0_sm[wm * 32 + m * 16 + (lane >> 2)]     = acc[m][0][0];
                    y0_sm[wm * 32 + m * 16 + 8 + (lane >> 2)] = acc[m][0][2];
                }
            }
            #pragma unroll
            for (int m = 0; m < 2; ++m)
                #pragma unroll
                for (int h = 0; h < 2; ++h) {
                    float v = p[m][h];
                    v += __shfl_xor_sync(0xffffffffu, v, 1);
                    v += __shfl_xor_sync(0xffffffffu, v, 2);
                    if ((lane & 3) == 0)
                        atomicAdd(&part[wm * 32 + m * 16 + h * 8 + (lane >> 2)], v);
                }
            // stash biased (unscaled) y to gmem; rescaled in place at the end
            #pragma unroll
            for (int m = 0; m < 2; ++m) {
                const int rlo = wm * 32 + m * 16 + (lane >> 2);
                #pragma unroll
                for (int f = 0; f < 8; ++f) {
                    const int c = wn * 64 + f * 8 + (lane & 3) * 2;
                    *reinterpret_cast<float2*>(out + (size_t)(row0 + rlo) * ND + c) =
                        make_float2(acc[m][f][0], acc[m][f][1]);
                    *reinterpret_cast<float2*>(out + (size_t)(row0 + rlo + 8) * ND + c) =
                        make_float2(acc[m][f][2], acc[m][f][3]);
                }
            }
            #pragma unroll
            for (int m = 0; m < 2; ++m)
                #pragma unroll
                for (int f = 0; f < 8; ++f)
                    #pragma unroll
                    for (int k = 0; k < 4; ++k) acc[m][f][k] = 0.f;
        }
    }
    #undef ISSUE

    // ---- chunk-1 epilogue: bias + ssq into part ----
    {
        float p[2][2] = {{0.f, 0.f}, {0.f, 0.f}};
        #pragma unroll
        for (int m = 0; m < 2; ++m) {
            #pragma unroll
            for (int f = 0; f < 8; ++f) {
                const int col = 256 + wn * 64 + f * 8 + (lane & 3) * 2;
                const float2 bv = __ldg(reinterpret_cast<const float2*>(bias + col));
                acc[m][f][0] += bv.x; acc[m][f][1] += bv.y;
                acc[m][f][2] += bv.x; acc[m][f][3] += bv.y;
                p[m][0] += acc[m][f][0] * acc[m][f][0] + acc[m][f][1] * acc[m][f][1];
                p[m][1] += acc[m][f][2] * acc[m][f][2] + acc[m][f][3] * acc[m][f][3];
            }
        }
        #pragma unroll
        for (int m = 0; m < 2; ++m)
            #pragma unroll
            for (int h = 0; h < 2; ++h) {
                float v = p[m][h];
                v += __shfl_xor_sync(0xffffffffu, v, 1);
                v += __shfl_xor_sync(0xffffffffu, v, 2);
                if ((lane & 3) == 0)
                    atomicAdd(&part[wm * 32 + m * 16 + h * 8 + (lane >> 2)], v);
            }
    }
    __syncthreads();

    // ---- per-row scalars ----
    if (tid < 128) {
        const int r = tid;
        const float tot = part[r];
        const float y0 = y0_sm[r];
        const float es = expf(scale[0]);
        const float t  = es / (1.f + expf(-y0)) + 1.1f;
        const float rr = sqrtf((t * t - 1.f) / fmaxf(tot, 1e-8f));
        r_sm[r] = rr;
        t_sm[r] = t;
    }
    __syncthreads();

    // ---- write chunk 1 (cols 256..511) from registers, scaled ----
    #pragma unroll
    for (int m = 0; m < 2; ++m) {
        const int rlo = wm * 32 + m * 16 + (lane >> 2);
        const float rr0 = r_sm[rlo], rr1 = r_sm[rlo + 8];
        #pragma unroll
        for (int f = 0; f < 8; ++f) {
            const int c = 256 + wn * 64 + f * 8 + (lane & 3) * 2;
            *reinterpret_cast<float2*>(out + (size_t)(row0 + rlo) * ND + c) =
                make_float2(acc[m][f][0] * rr0, acc[m][f][1] * rr0);
            *reinterpret_cast<float2*>(out + (size_t)(row0 + rlo + 8) * ND + c) =
                make_float2(acc[m][f][2] * rr1, acc[m][f][3] * rr1);
        }
    }

    // ---- rescale chunk 0 (cols 0..255) in place (L2-hot) ----
    #pragma unroll 4
    for (int i = tid; i < 128 * 64; i += THREADS) {
        const int r  = i >> 6;
        const int c4 = (i & 63) * 4;
        const float rr = r_sm[r];
        float* p4 = out + (size_t)(row0 + r) * ND + c4;
        float4 v = *reinterpret_cast<float4*>(p4);
        v.x *= rr; v.y *= rr; v.z *= rr; v.w *= rr;
        if (c4 == 0) v.x = t_sm[r];
        *reinterpret_cast<float4*>(p4) = v;
    }
}

// ---------------- launch ----------------

extern "C" void kernel_launch(void* const* d_in, const int* in_sizes, int n_in,
                              void* d_out, int out_size) {
    const float* x     = (const float*)d_in[0];
    const float* W     = (const float*)d_in[1];
    const float* b     = (const float*)d_in[2];
    const float* scale = (const float*)d_in[3];
    float* out = (float*)d_out;

    const int wunits = ND * KD / 8;                 // 32768
    cvtW_kernel<<<(wunits + 255) / 256, 256>>>(W);

    const int rows = in_sizes[0] / KD;              // 65536
    const int grid = rows / BM;                     // 512
    cudaFuncSetAttribute(lorentz_kernel,
                         cudaFuncAttributeMaxDynamicSharedMemorySize, SMEM_TOTAL);
    lorentz_kernel<<<grid, THREADS, SMEM_TOTAL>>>(x, b, scale, out);
}

// round 10
// speedup vs baseline: 1.5034x; 1.1282x over previous
#include <cuda_runtime.h>
#include <cuda_fp16.h>
#include <cstdint>
#include <math.h>

// ----------------------------------------------------------------------------
// LorentzLinear R7: 2 CTAs/SM for latency/barrier overlap.
//  - W pre-converted f32->fp16 (tiny kernel).
//  - CTA = 64 rows x 512 cols (256 thr, 8 warps: wm 2 x wn 4).
//  - A panel (64x512 fp16, 64KB) converted in-kernel, resident.
//  - B: flat 32-iteration cp.async pipeline (KT=32, 3 stages, 16KB/stage),
//    one syncthreads/iter; chunk-0 epilogue inline at j==15.
//  - Lorentz epilogue fused; chunk-0 stashed to gmem, rescaled in place.
// ----------------------------------------------------------------------------

#define THREADS 256
#define BM      64
#define KD      512
#define ND      512
#define KT      32
#define NTOT    32          // 2 chunks x 16 k-tiles
#define NST     3
#define NROWS   65536

__device__ __half g_wh[ND * KD];

// smem layout (bytes)
#define OFF_APAN 0
#define APAN_SZ  (64 * 1024)             // 64 rows x 512 fp16, swizzled
#define OFF_B    APAN_SZ                 // 65536
#define BST      16384                   // 256 rows x 64B, 2-row-block swizzle
#define OFF_PART (OFF_B + NST * BST)     // 114688; float[64], reused as r_sm
#define OFF_Y0T  (OFF_PART + 256)        // float[64], y0 then t
#define SMEM_TOTAL (OFF_Y0T + 256)       // 115200 -> 2 CTAs = 230400

__device__ __forceinline__ uint32_t smem_u32(const void* p) {
    uint32_t a;
    asm("{ .reg .u64 t; cvta.to.shared.u64 t, %1; cvt.u32.u64 %0, t; }"
        : "=r"(a) : "l"(p));
    return a;
}

__device__ __forceinline__ void ldm4(uint32_t r[4], uint32_t addr) {
    asm volatile("ldmatrix.sync.aligned.m8n8.x4.shared.b16 {%0,%1,%2,%3}, [%4];"
                 : "=r"(r[0]), "=r"(r[1]), "=r"(r[2]), "=r"(r[3]) : "r"(addr));
}

__device__ __forceinline__ void mma16816(float c[4], const uint32_t a[4],
                                         uint32_t b0, uint32_t b1) {
    asm volatile(
        "mma.sync.aligned.m16n8k16.row.col.f32.f16.f16.f32 "
        "{%0,%1,%2,%3}, {%4,%5,%6,%7}, {%8,%9}, {%0,%1,%2,%3};"
        : "+f"(c[0]), "+f"(c[1]), "+f"(c[2]), "+f"(c[3])
        : "r"(a[0]), "r"(a[1]), "r"(a[2]), "r"(a[3]), "r"(b0), "r"(b1));
}

__device__ __forceinline__ void cp16(uint32_t smem_dst, const void* gsrc) {
    asm volatile("cp.async.cg.shared.global [%0], [%1], 16;"
                 :: "r"(smem_dst), "l"(gsrc));
}
#define CP_COMMIT() asm volatile("cp.async.commit_group;" ::: "memory")
#define CP_WAIT1()  asm volatile("cp.async.wait_group 1;" ::: "memory")

__device__ __forceinline__ void sts128(uint32_t addr, uint32_t r0, uint32_t r1,
                                       uint32_t r2, uint32_t r3) {
    asm volatile("st.shared.v4.b32 [%0], {%1,%2,%3,%4};"
                 :: "r"(addr), "r"(r0), "r"(r1), "r"(r2), "r"(r3) : "memory");
}

// ---------------- kernel A: W f32 -> f16 ----------------

__global__ void __launch_bounds__(256)
cvtW_kernel(const float* __restrict__ W) {
    const size_t u = (size_t)blockIdx.x * 256 + threadIdx.x;
    if (u >= (size_t)ND * KD / 8) return;
    const float* src = W + u * 8;
    float4 v0 = *reinterpret_cast<const float4*>(src);
    float4 v1 = *reinterpret_cast<const float4*>(src + 4);
    __half2 h[4];
    h[0] = __floats2half2_rn(v0.x, v0.y);
    h[1] = __floats2half2_rn(v0.z, v0.w);
    h[2] = __floats2half2_rn(v1.x, v1.y);
    h[3] = __floats2half2_rn(v1.z, v1.w);
    *reinterpret_cast<uint4*>(g_wh + u * 8) = *reinterpret_cast<uint4*>(h);
}

// ---------------- main kernel ----------------

__global__ void __launch_bounds__(THREADS, 2)
lorentz_kernel(const float* __restrict__ x, const float* __restrict__ bias,
               const float* __restrict__ scale, float* __restrict__ out) {
    extern __shared__ char smem[];
    const uint32_t sb = smem_u32(smem);
    const int tid  = threadIdx.x;
    const int lane = tid & 31;
    const int w    = tid >> 5;          // 0..7
    const int wm   = w >> 2;            // 0..1 (32 rows each)
    const int wn   = w & 3;             // 0..3 (64 cols each)
    const int l15  = lane & 15;
    const int hi   = lane >> 4;
    const int row0 = blockIdx.x * BM;

    float* part = (float*)(smem + OFF_PART);   // ssq partials -> r_sm
    float* y0t  = (float*)(smem + OFF_Y0T);    // y0 -> t

    if (tid < 64) part[tid] = 0.f;

    // ---- B cp.async addressing: 1024 16B units/stage, 4 per thread ----
    // stage layout: addr(row,cu) = (row>>1)*128 + (((row&1)*4+cu)^((row>>1)&7))*16
    const int bt_row = tid >> 2, bt_cu = tid & 3;
    const uint32_t bDst0 = sb + OFF_B + (bt_row >> 1) * 128
        + (((uint32_t)((bt_row & 1) * 4 + bt_cu) ^ ((bt_row >> 1) & 7)) << 4);
    const __half* wSrc0 = g_wh + (size_t)bt_row * KD + bt_cu * 8;

    #define ISSUE(J) do {                                                     \
        const int _j = (J);                                                   \
        if (_j < NTOT) {                                                      \
            const int _st = _j % NST;                                         \
            const __half* _src = wSrc0 + (size_t)(_j >> 4) * 256 * KD         \
                                       + (_j & 15) * KT;                      \
            _Pragma("unroll")                                                 \
            for (int _jj = 0; _jj < 4; ++_jj)                                 \
                cp16(bDst0 + _st * BST + _jj * 4096,                          \
                     _src + (size_t)_jj * 64 * KD);                           \
        }                                                                     \
        CP_COMMIT();                                                          \
    } while (0)

    ISSUE(0);
    ISSUE(1);

    // ---- A panel: convert 64x512 f32 -> fp16 smem (4096 units, 16/thread) ----
    #pragma unroll
    for (int i = 0; i < 16; ++i) {
        const int u   = tid + i * THREADS;
        const int row = u >> 6, cu = u & 63;
        const float* src = x + (size_t)(row0 + row) * KD + cu * 8;
        float4 v0 = *reinterpret_cast<const float4*>(src);
        float4 v1 = *reinterpret_cast<const float4*>(src + 4);
        __half2 h0 = __floats2half2_rn(v0.x, v0.y);
        __half2 h1 = __floats2half2_rn(v0.z, v0.w);
        __half2 h2 = __floats2half2_rn(v1.x, v1.y);
        __half2 h3 = __floats2half2_rn(v1.z, v1.w);
        const uint32_t dst = sb + OFF_APAN + row * 1024 + ((cu ^ (row & 7)) << 4);
        sts128(dst, *(uint32_t*)&h0, *(uint32_t*)&h1,
                    *(uint32_t*)&h2, *(uint32_t*)&h3);
    }
    __syncthreads();

    // ---- ldmatrix addressing ----
    const uint32_t aRow  = wm * 32 + l15;              // +16 for m=1
    const uint32_t aBase = sb + OFF_APAN + aRow * 1024;
    const uint32_t ka    = aRow & 7;
    const uint32_t bBase = sb + OFF_B + (wn * 32 + (l15 >> 1)) * 128;
    const uint32_t kbm   = (l15 >> 1) & 7;
    const uint32_t bhb   = (l15 & 1) * 4;
    const uint32_t bxo0  = (((bhb + 0 + hi) ^ kbm) << 4);
    const uint32_t bxo1  = (((bhb + 2 + hi) ^ kbm) << 4);

    float acc[2][8][4];
    #pragma unroll
    for (int m = 0; m < 2; ++m)
        #pragma unroll
        for (int f = 0; f < 8; ++f)
            #pragma unroll
            for (int k = 0; k < 4; ++k) acc[m][f][k] = 0.f;

    // ---- flat mainloop: 32 iterations over both N-chunks ----
    #pragma unroll 1
    for (int j = 0; j < NTOT; ++j) {
        const int st = j % NST;
        CP_WAIT1();
        __syncthreads();
        ISSUE(j + 2);

        const uint32_t bS = bBase + st * BST;
        #pragma unroll
        for (int ks = 0; ks < 2; ++ks) {
            const uint32_t u  = (uint32_t)((j & 15) * 4 + ks * 2 + hi);
            const uint32_t axo = ((u ^ ka) << 4);
            uint32_t a0[4], a1[4];
            ldm4(a0, aBase + axo);
            ldm4(a1, aBase + 16 * 1024 + axo);
            const uint32_t bxo = ks ? bxo1 : bxo0;
            #pragma unroll
            for (int g = 0; g < 4; ++g) {
                uint32_t bb[4];
                ldm4(bb, bS + g * 1024 + bxo);
                mma16816(acc[0][2 * g],     a0, bb[0], bb[2]);
                mma16816(acc[0][2 * g + 1], a0, bb[1], bb[3]);
                mma16816(acc[1][2 * g],     a1, bb[0], bb[2]);
                mma16816(acc[1][2 * g + 1], a1, bb[1], bb[3]);
            }
        }

        if (j == 15) {
            // ---- chunk-0 epilogue (cols 0..255): bias, ssq, stash, reset ----
            float p[2][2] = {{0.f, 0.f}, {0.f, 0.f}};
            #pragma unroll
            for (int m = 0; m < 2; ++m) {
                #pragma unroll
                for (int f = 0; f < 8; ++f) {
                    const int col = wn * 64 + f * 8 + (lane & 3) * 2;
                    const float2 bv = __ldg(reinterpret_cast<const float2*>(bias + col));
                    acc[m][f][0] += bv.x; acc[m][f][1] += bv.y;
                    acc[m][f][2] += bv.x; acc[m][f][3] += bv.y;
                    p[m][0] += acc[m][f][0] * acc[m][f][0] + acc[m][f][1] * acc[m][f][1];
                    p[m][1] += acc[m][f][2] * acc[m][f][2] + acc[m][f][3] * acc[m][f][3];
                }
            }
            if (wn == 0 && (lane & 3) == 0) {
                #pragma unroll
                for (int m = 0; m < 2; ++m) {
                    p[m][0] -= acc[m][0][0] * acc[m][0][0];
                    p[m][1] -= acc[m][0][2] * acc[m][0][2];
                    y0t[wm * 32 + m * 16 + (lane >> 2)]     = acc[m][0][0];
                    y0t[wm * 32 + m * 16 + 8 + (lane >> 2)] = acc[m][0][2];
                }
            }
            #pragma unroll
            for (int m = 0; m < 2; ++m)
                #pragma unroll
                for (int h = 0; h < 2; ++h) {
                    float v = p[m][h];
                    v += __shfl_xor_sync(0xffffffffu, v, 1);
                    v += __shfl_xor_sync(0xffffffffu, v, 2);
                    if ((lane & 3) == 0)
                        atomicAdd(&part[wm * 32 + m * 16 + h * 8 + (lane >> 2)], v);
                }
            #pragma unroll
            for (int m = 0; m < 2; ++m) {
                const int rlo = wm * 32 + m * 16 + (lane >> 2);
                #pragma unroll
                for (int f = 0; f < 8; ++f) {
                    const int c = wn * 64 + f * 8 + (lane & 3) * 2;
                    *reinterpret_cast<float2*>(out + (size_t)(row0 + rlo) * ND + c) =
                        make_float2(acc[m][f][0], acc[m][f][1]);
                    *reinterpret_cast<float2*>(out + (size_t)(row0 + rlo + 8) * ND + c) =
                        make_float2(acc[m][f][2], acc[m][f][3]);
                }
            }
            #pragma unroll
            for (int m = 0; m < 2; ++m)
                #pragma unroll
                for (int f = 0; f < 8; ++f)
                    #pragma unroll
                    for (int k = 0; k < 4; ++k) acc[m][f][k] = 0.f;
        }
    }
    #undef ISSUE

    // ---- chunk-1 epilogue: bias + ssq ----
    {
        float p[2][2] = {{0.f, 0.f}, {0.f, 0.f}};
        #pragma unroll
        for (int m = 0; m < 2; ++m) {
            #pragma unroll
            for (int f = 0; f < 8; ++f) {
                const int col = 256 + wn * 64 + f * 8 + (lane & 3) * 2;
                const float2 bv = __ldg(reinterpret_cast<const float2*>(bias + col));
                acc[m][f][0] += bv.x; acc[m][f][1] += bv.y;
                acc[m][f][2] += bv.x; acc[m][f][3] += bv.y;
                p[m][0] += acc[m][f][0] * acc[m][f][0] + acc[m][f][1] * acc[m][f][1];
                p[m][1] += acc[m][f][2] * acc[m][f][2] + acc[m][f][3] * acc[m][f][3];
            }
        }
        #pragma unroll
        for (int m = 0; m < 2; ++m)
            #pragma unroll
            for (int h = 0; h < 2; ++h) {
                float v = p[m][h];
                v += __shfl_xor_sync(0xffffffffu, v, 1);
                v += __shfl_xor_sync(0xffffffffu, v, 2);
                if ((lane & 3) == 0)
                    atomicAdd(&part[wm * 32 + m * 16 + h * 8 + (lane >> 2)], v);
            }
    }
    __syncthreads();

    // ---- per-row scalars (part -> r, y0t -> t) ----
    if (tid < 64) {
        const float tot = part[tid];
        const float y0 = y0t[tid];
        const float es = expf(scale[0]);
        const float t  = es / (1.f + expf(-y0)) + 1.1f;
        const float rr = sqrtf((t * t - 1.f) / fmaxf(tot, 1e-8f));
        part[tid] = rr;
        y0t[tid]  = t;
    }
    __syncthreads();

    // ---- write chunk 1 (cols 256..511) from registers, scaled ----
    #pragma unroll
    for (int m = 0; m < 2; ++m) {
        const int rlo = wm * 32 + m * 16 + (lane >> 2);
        const float rr0 = part[rlo], rr1 = part[rlo + 8];
        #pragma unroll
        for (int f = 0; f < 8; ++f) {
            const int c = 256 + wn * 64 + f * 8 + (lane & 3) * 2;
            *reinterpret_cast<float2*>(out + (size_t)(row0 + rlo) * ND + c) =
                make_float2(acc[m][f][0] * rr0, acc[m][f][1] * rr0);
            *reinterpret_cast<float2*>(out + (size_t)(row0 + rlo + 8) * ND + c) =
                make_float2(acc[m][f][2] * rr1, acc[m][f][3] * rr1);
        }
    }

    // ---- rescale chunk 0 (cols 0..255) in place (L2-hot) ----
    #pragma unroll 4
    for (int i = tid; i < 64 * 64; i += THREADS) {
        const int r  = i >> 6;
        const int c4 = (i & 63) * 4;
        const float rr = part[r];
        float* p4 = out + (size_t)(row0 + r) * ND + c4;
        float4 v = *reinterpret_cast<float4*>(p4);
        v.x *= rr; v.y *= rr; v.z *= rr; v.w *= rr;
        if (c4 == 0) v.x = y0t[r];
        *reinterpret_cast<float4*>(p4) = v;
    }
}

// ---------------- launch ----------------

extern "C" void kernel_launch(void* const* d_in, const int* in_sizes, int n_in,
                              void* d_out, int out_size) {
    const float* x     = (const float*)d_in[0];
    const float* W     = (const float*)d_in[1];
    const float* b     = (const float*)d_in[2];
    const float* scale = (const float*)d_in[3];
    float* out = (float*)d_out;

    const int wunits = ND * KD / 8;
    cvtW_kernel<<<(wunits + 255) / 256, 256>>>(W);

    const int rows = in_sizes[0] / KD;     // 65536
    const int grid = rows / BM;            // 1024
    cudaFuncSetAttribute(lorentz_kernel,
                         cudaFuncAttributeMaxDynamicSharedMemorySize, SMEM_TOTAL);
    lorentz_kernel<<<grid, THREADS, SMEM_TOTAL>>>(x, b, scale, out);
}

// round 11
// speedup vs baseline: 1.5632x; 1.0398x over previous
#include <cuda_runtime.h>
#include <cuda_fp16.h>
#include <cstdint>
#include <math.h>

// ----------------------------------------------------------------------------
// LorentzLinear R11: R7 (2 CTAs/SM, resident A panel, flat B pipeline)
//  + W scratch is pre-TILED and pre-SWIZZLED into exact smem-stage images:
//    tile j = contiguous 16KB block, so the mainloop B copy is a linear
//    cp.async with zero address arithmetic (kills the ALU-pipe contention).
// ----------------------------------------------------------------------------

#define THREADS 256
#define BM      64
#define KD      512
#define ND      512
#define KT      32
#define NTOT    32          // 2 chunks x 16 k-tiles
#define NST     3
#define NROWS   65536

// W scratch: 32 tiles x 16KB stage images = 512KB, 16B units
__device__ uint4 g_wt[32 * 1024];

// smem layout (bytes)
#define OFF_APAN 0
#define APAN_SZ  (64 * 1024)             // 64 rows x 512 fp16, swizzled
#define OFF_B    APAN_SZ                 // 65536
#define BST      16384
#define OFF_PART (OFF_B + NST * BST)     // 114688; float[64] ssq -> r
#define OFF_Y0T  (OFF_PART + 256)        // float[64] y0 -> t
#define SMEM_TOTAL (OFF_Y0T + 256)       // 115200 -> 2 CTAs = 230400

__device__ __forceinline__ uint32_t smem_u32(const void* p) {
    uint32_t a;
    asm("{ .reg .u64 t; cvta.to.shared.u64 t, %1; cvt.u32.u64 %0, t; }"
        : "=r"(a) : "l"(p));
    return a;
}

__device__ __forceinline__ void ldm4(uint32_t r[4], uint32_t addr) {
    asm volatile("ldmatrix.sync.aligned.m8n8.x4.shared.b16 {%0,%1,%2,%3}, [%4];"
                 : "=r"(r[0]), "=r"(r[1]), "=r"(r[2]), "=r"(r[3]) : "r"(addr));
}

__device__ __forceinline__ void mma16816(float c[4], const uint32_t a[4],
                                         uint32_t b0, uint32_t b1) {
    asm volatile(
        "mma.sync.aligned.m16n8k16.row.col.f32.f16.f16.f32 "
        "{%0,%1,%2,%3}, {%4,%5,%6,%7}, {%8,%9}, {%0,%1,%2,%3};"
        : "+f"(c[0]), "+f"(c[1]), "+f"(c[2]), "+f"(c[3])
        : "r"(a[0]), "r"(a[1]), "r"(a[2]), "r"(a[3]), "r"(b0), "r"(b1));
}

__device__ __forceinline__ void cp16(uint32_t smem_dst, const void* gsrc) {
    asm volatile("cp.async.cg.shared.global [%0], [%1], 16;"
                 :: "r"(smem_dst), "l"(gsrc));
}
#define CP_COMMIT() asm volatile("cp.async.commit_group;" ::: "memory")
#define CP_WAIT1()  asm volatile("cp.async.wait_group 1;" ::: "memory")

__device__ __forceinline__ void sts128(uint32_t addr, uint32_t r0, uint32_t r1,
                                       uint32_t r2, uint32_t r3) {
    asm volatile("st.shared.v4.b32 [%0], {%1,%2,%3,%4};"
                 :: "r"(addr), "r"(r0), "r"(r1), "r"(r2), "r"(r3) : "memory");
}

// ---------------- kernel A: W f32 -> fp16, tiled+swizzled stage images ------
// Stage image (16KB) for tile j (chunk=j>>4, kt=j&15), byte offset `off`:
//   jj = off>>12, q = off&4095, p = q>>7, swz = (q>>4)&7
//   cu6 = swz ^ (p&7); half = cu6>>2; cu = cu6&3
//   W row = chunk*256 + jj*64 + p*2 + half;  k = kt*32 + cu*8   (8 halves)

__global__ void __launch_bounds__(256)
cvtW_kernel(const float* __restrict__ W) {
    const uint32_t u = blockIdx.x * 256 + threadIdx.x;    // 16B unit index
    if (u >= 32 * 1024) return;
    const uint32_t j   = u >> 10;
    const uint32_t off = (u & 1023) << 4;
    const uint32_t jj  = off >> 12;
    const uint32_t q   = off & 4095;
    const uint32_t p   = q >> 7;
    const uint32_t swz = (q >> 4) & 7;
    const uint32_t cu6 = swz ^ (p & 7);
    const uint32_t wrow = (j >> 4) * 256 + jj * 64 + p * 2 + (cu6 >> 2);
    const uint32_t k0   = (j & 15) * 32 + (cu6 & 3) * 8;
    const float* src = W + (size_t)wrow * KD + k0;
    float4 v0 = *reinterpret_cast<const float4*>(src);
    float4 v1 = *reinterpret_cast<const float4*>(src + 4);
    __half2 h[4];
    h[0] = __floats2half2_rn(v0.x, v0.y);
    h[1] = __floats2half2_rn(v0.z, v0.w);
    h[2] = __floats2half2_rn(v1.x, v1.y);
    h[3] = __floats2half2_rn(v1.z, v1.w);
    g_wt[u] = *reinterpret_cast<uint4*>(h);
}

// ---------------- main kernel ----------------

__global__ void __launch_bounds__(THREADS, 2)
lorentz_kernel(const float* __restrict__ x, const float* __restrict__ bias,
               const float* __restrict__ scale, float* __restrict__ out) {
    extern __shared__ char smem[];
    const uint32_t sb = smem_u32(smem);
    const int tid  = threadIdx.x;
    const int lane = tid & 31;
    const int w    = tid >> 5;
    const int wm   = w >> 2;
    const int wn   = w & 3;
    const int l15  = lane & 15;
    const int hi   = lane >> 4;
    const int row0 = blockIdx.x * BM;

    float* part = (float*)(smem + OFF_PART);
    float* y0t  = (float*)(smem + OFF_Y0T);

    if (tid < 64) part[tid] = 0.f;

    // ---- linear B copy: thread copies units tid + jj*256 of each tile ----
    const uint32_t bDstL = sb + OFF_B + tid * 16;

    #define ISSUE(J) do {                                                     \
        const int _j = (J);                                                   \
        if (_j < NTOT) {                                                      \
            const int _st = _j % NST;                                         \
            const uint4* _src = g_wt + _j * 1024 + tid;                       \
            const uint32_t _d = bDstL + _st * BST;                            \
            _Pragma("unroll")                                                 \
            for (int _jj = 0; _jj < 4; ++_jj)                                 \
                cp16(_d + _jj * 4096, _src + _jj * 256);                      \
        }                                                                     \
        CP_COMMIT();                                                          \
    } while (0)

    ISSUE(0);
    ISSUE(1);

    // ---- A panel: convert 64x512 f32 -> fp16 smem (4096 units, 16/thread) --
    #pragma unroll
    for (int i = 0; i < 16; ++i) {
        const int u   = tid + i * THREADS;
        const int row = u >> 6, cu = u & 63;
        const float* src = x + (size_t)(row0 + row) * KD + cu * 8;
        float4 v0 = *reinterpret_cast<const float4*>(src);
        float4 v1 = *reinterpret_cast<const float4*>(src + 4);
        __half2 h0 = __floats2half2_rn(v0.x, v0.y);
        __half2 h1 = __floats2half2_rn(v0.z, v0.w);
        __half2 h2 = __floats2half2_rn(v1.x, v1.y);
        __half2 h3 = __floats2half2_rn(v1.z, v1.w);
        const uint32_t dst = sb + OFF_APAN + row * 1024 + ((cu ^ (row & 7)) << 4);
        sts128(dst, *(uint32_t*)&h0, *(uint32_t*)&h1,
                    *(uint32_t*)&h2, *(uint32_t*)&h3);
    }
    __syncthreads();

    // ---- ldmatrix addressing (layout identical to R7) ----
    const uint32_t aRow  = wm * 32 + l15;
    const uint32_t aBase = sb + OFF_APAN + aRow * 1024;
    const uint32_t ka    = aRow & 7;
    const uint32_t bBase = sb + OFF_B + (wn * 32 + (l15 >> 1)) * 128;
    const uint32_t kbm   = (l15 >> 1) & 7;
    const uint32_t bhb   = (l15 & 1) * 4;
    const uint32_t bxo0  = (((bhb + 0 + hi) ^ kbm) << 4);
    const uint32_t bxo1  = (((bhb + 2 + hi) ^ kbm) << 4);

    float acc[2][8][4];
    #pragma unroll
    for (int m = 0; m < 2; ++m)
        #pragma unroll
        for (int f = 0; f < 8; ++f)
            #pragma unroll
            for (int k = 0; k < 4; ++k) acc[m][f][k] = 0.f;

    // ---- flat mainloop: 32 iterations over both N-chunks ----
    #pragma unroll 1
    for (int j = 0; j < NTOT; ++j) {
        const int st = j % NST;
        CP_WAIT1();
        __syncthreads();
        ISSUE(j + 2);

        const uint32_t bS = bBase + st * BST;
        #pragma unroll
        for (int ks = 0; ks < 2; ++ks) {
            const uint32_t u  = (uint32_t)((j & 15) * 4 + ks * 2 + hi);
            const uint32_t axo = ((u ^ ka) << 4);
            uint32_t a0[4], a1[4];
            ldm4(a0, aBase + axo);
            ldm4(a1, aBase + 16 * 1024 + axo);
            const uint32_t bxo = ks ? bxo1 : bxo0;
            #pragma unroll
            for (int g = 0; g < 4; ++g) {
                uint32_t bb[4];
                ldm4(bb, bS + g * 1024 + bxo);
                mma16816(acc[0][2 * g],     a0, bb[0], bb[2]);
                mma16816(acc[0][2 * g + 1], a0, bb[1], bb[3]);
                mma16816(acc[1][2 * g],     a1, bb[0], bb[2]);
                mma16816(acc[1][2 * g + 1], a1, bb[1], bb[3]);
            }
        }

        if (j == 15) {
            // ---- chunk-0 epilogue (cols 0..255): bias, ssq, stash, reset ----
            float p[2][2] = {{0.f, 0.f}, {0.f, 0.f}};
            #pragma unroll
            for (int m = 0; m < 2; ++m) {
                #pragma unroll
                for (int f = 0; f < 8; ++f) {
                    const int col = wn * 64 + f * 8 + (lane & 3) * 2;
                    const float2 bv = __ldg(reinterpret_cast<const float2*>(bias + col));
                    acc[m][f][0] += bv.x; acc[m][f][1] += bv.y;
                    acc[m][f][2] += bv.x; acc[m][f][3] += bv.y;
                    p[m][0] += acc[m][f][0] * acc[m][f][0] + acc[m][f][1] * acc[m][f][1];
                    p[m][1] += acc[m][f][2] * acc[m][f][2] + acc[m][f][3] * acc[m][f][3];
                }
            }
            if (wn == 0 && (lane & 3) == 0) {
                #pragma unroll
                for (int m = 0; m < 2; ++m) {
                    p[m][0] -= acc[m][0][0] * acc[m][0][0];
                    p[m][1] -= acc[m][0][2] * acc[m][0][2];
                    y0t[wm * 32 + m * 16 + (lane >> 2)]     = acc[m][0][0];
                    y0t[wm * 32 + m * 16 + 8 + (lane >> 2)] = acc[m][0][2];
                }
            }
            #pragma unroll
            for (int m = 0; m < 2; ++m)
                #pragma unroll
                for (int h = 0; h < 2; ++h) {
                    float v = p[m][h];
                    v += __shfl_xor_sync(0xffffffffu, v, 1);
                    v += __shfl_xor_sync(0xffffffffu, v, 2);
                    if ((lane & 3) == 0)
                        atomicAdd(&part[wm * 32 + m * 16 + h * 8 + (lane >> 2)], v);
                }
            #pragma unroll
            for (int m = 0; m < 2; ++m) {
                const int rlo = wm * 32 + m * 16 + (lane >> 2);
                #pragma unroll
                for (int f = 0; f < 8; ++f) {
                    const int c = wn * 64 + f * 8 + (lane & 3) * 2;
                    *reinterpret_cast<float2*>(out + (size_t)(row0 + rlo) * ND + c) =
                        make_float2(acc[m][f][0], acc[m][f][1]);
                    *reinterpret_cast<float2*>(out + (size_t)(row0 + rlo + 8) * ND + c) =
                        make_float2(acc[m][f][2], acc[m][f][3]);
                }
            }
            #pragma unroll
            for (int m = 0; m < 2; ++m)
                #pragma unroll
                for (int f = 0; f < 8; ++f)
                    #pragma unroll
                    for (int k = 0; k < 4; ++k) acc[m][f][k] = 0.f;
        }
    }
    #undef ISSUE

    // ---- chunk-1 epilogue: bias + ssq ----
    {
        float p[2][2] = {{0.f, 0.f}, {0.f, 0.f}};
        #pragma unroll
        for (int m = 0; m < 2; ++m) {
            #pragma unroll
            for (int f = 0; f < 8; ++f) {
                const int col = 256 + wn * 64 + f * 8 + (lane & 3) * 2;
                const float2 bv = __ldg(reinterpret_cast<const float2*>(bias + col));
                acc[m][f][0] += bv.x; acc[m][f][1] += bv.y;
                acc[m][f][2] += bv.x; acc[m][f][3] += bv.y;
                p[m][0] += acc[m][f][0] * acc[m][f][0] + acc[m][f][1] * acc[m][f][1];
                p[m][1] += acc[m][f][2] * acc[m][f][2] + acc[m][f][3] * acc[m][f][3];
            }
        }
        #pragma unroll
        for (int m = 0; m < 2; ++m)
            #pragma unroll
            for (int h = 0; h < 2; ++h) {
                float v = p[m][h];
                v += __shfl_xor_sync(0xffffffffu, v, 1);
                v += __shfl_xor_sync(0xffffffffu, v, 2);
                if ((lane & 3) == 0)
                    atomicAdd(&part[wm * 32 + m * 16 + h * 8 + (lane >> 2)], v);
            }
    }
    __syncthreads();

    // ---- per-row scalars ----
    if (tid < 64) {
        const float tot = part[tid];
        const float y0 = y0t[tid];
        const float es = expf(scale[0]);
        const float t  = es / (1.f + expf(-y0)) + 1.1f;
        const float rr = sqrtf((t * t - 1.f) / fmaxf(tot, 1e-8f));
        part[tid] = rr;
        y0t[tid]  = t;
    }
    __syncthreads();

    // ---- write chunk 1 (cols 256..511) from registers, scaled ----
    #pragma unroll
    for (int m = 0; m < 2; ++m) {
        const int rlo = wm * 32 + m * 16 + (lane >> 2);
        const float rr0 = part[rlo], rr1 = part[rlo + 8];
        #pragma unroll
        for (int f = 0; f < 8; ++f) {
            const int c = 256 + wn * 64 + f * 8 + (lane & 3) * 2;
            *reinterpret_cast<float2*>(out + (size_t)(row0 + rlo) * ND + c) =
                make_float2(acc[m][f][0] * rr0, acc[m][f][1] * rr0);
            *reinterpret_cast<float2*>(out + (size_t)(row0 + rlo + 8) * ND + c) =
                make_float2(acc[m][f][2] * rr1, acc[m][f][3] * rr1);
        }
    }

    // ---- rescale chunk 0 (cols 0..255) in place (L2-hot) ----
    #pragma unroll 4
    for (int i = tid; i < 64 * 64; i += THREADS) {
        const int r  = i >> 6;
        const int c4 = (i & 63) * 4;
        const float rr = part[r];
        float* p4 = out + (size_t)(row0 + r) * ND + c4;
        float4 v = *reinterpret_cast<float4*>(p4);
        v.x *= rr; v.y *= rr; v.z *= rr; v.w *= rr;
        if (c4 == 0) v.x = y0t[r];
        *reinterpret_cast<float4*>(p4) = v;
    }
}

// ---------------- launch ----------------

extern "C" void kernel_launch(void* const* d_in, const int* in_sizes, int n_in,
                              void* d_out, int out_size) {
    const float* x     = (const float*)d_in[0];
    const float* W     = (const float*)d_in[1];
    const float* b     = (const float*)d_in[2];
    const float* scale = (const float*)d_in[3];
    float* out = (float*)d_out;

    cvtW_kernel<<<(32 * 1024 + 255) / 256, 256>>>(W);

    const int rows = in_sizes[0] / KD;     // 65536
    const int grid = rows / BM;            // 1024
    cudaFuncSetAttribute(lorentz_kernel,
                         cudaFuncAttributeMaxDynamicSharedMemorySize, SMEM_TOTAL);
    lorentz_kernel<<<grid, THREADS, SMEM_TOTAL>>>(x, b, scale, out);
}